// round 6
// baseline (speedup 1.0000x reference)
#include <cuda_runtime.h>
#include <cuda_bf16.h>
#include <mma.h>
#include <cstdint>
#include <math.h>

using namespace nvcuda;

#define B_   128
#define N_   256
#define E_   2048
#define GTOT 256   // q graphs [0,128) + c graphs [128,256)

// ---------------- device scratch (static globals: no allocs) ----------------
__device__ float    g_bufA[GTOT * N_ * 128];   // 33.5 MB (gemm out / s matrix)
__device__ float    g_bufB[GTOT * N_ * 128];   // 33.5 MB (final embeddings)
__device__ __nv_bfloat16 g_Xhi[GTOT * N_ * 128];   // 16.8 MB bf16 hi activations
__device__ __nv_bfloat16 g_Xlo[GTOT * N_ * 128];   // 16.8 MB bf16 lo activations
__device__ __nv_bfloat16 g_Whi[26624];             // W1|W2|W3 bf16 hi
__device__ __nv_bfloat16 g_Wlo[26624];             // W1|W2|W3 bf16 lo
__device__ float2   g_edge[GTOT * E_];         // packed (coef, src-as-float-bits)
__device__ int      g_rowptr[GTOT * 257];
__device__ float    g_invdeg[GTOT * N_];
__device__ float    g_pool[GTOT * 32];
__device__ float    g_scoresT[B_ * 16];
__device__ unsigned g_minmax[2];
__device__ int      g_hist[16];

// monotone float<->uint mapping for atomicMin/Max over signed floats
__device__ __forceinline__ unsigned encf(float f) {
    unsigned u = __float_as_uint(f);
    return (u & 0x80000000u) ? ~u : (u | 0x80000000u);
}
__device__ __forceinline__ float decf(unsigned u) {
    return (u & 0x80000000u) ? __uint_as_float(u & 0x7fffffffu)
                             : __uint_as_float(~u);
}

// pack 4 floats -> (hi uint2, lo uint2) of bf16
__device__ __forceinline__ void split4(float4 v, uint2& hq, uint2& lq) {
    __nv_bfloat16 h0 = __float2bfloat16(v.x);
    __nv_bfloat16 h1 = __float2bfloat16(v.y);
    __nv_bfloat16 h2 = __float2bfloat16(v.z);
    __nv_bfloat16 h3 = __float2bfloat16(v.w);
    __nv_bfloat16 l0 = __float2bfloat16(v.x - __bfloat162float(h0));
    __nv_bfloat16 l1 = __float2bfloat16(v.y - __bfloat162float(h1));
    __nv_bfloat16 l2 = __float2bfloat16(v.z - __bfloat162float(h2));
    __nv_bfloat16 l3 = __float2bfloat16(v.w - __bfloat162float(h3));
    __nv_bfloat162 ph01(h0, h1), ph23(h2, h3), pl01(l0, l1), pl23(l2, l3);
    hq.x = *(unsigned*)&ph01; hq.y = *(unsigned*)&ph23;
    lq.x = *(unsigned*)&pl01; lq.y = *(unsigned*)&pl23;
}

// ---------------- input conversion: xq|xc fp32 -> bf16 hi/lo ----------------
__global__ void __launch_bounds__(256) k_cvtX(const float* __restrict__ xq,
                                              const float* __restrict__ xc) {
    constexpr size_t TOT4  = (size_t)GTOT * N_ * 128 / 4;   // 2,097,152
    constexpr size_t HALF4 = TOT4 / 2;
    uint2* Xhi = (uint2*)g_Xhi;
    uint2* Xlo = (uint2*)g_Xlo;
    for (size_t i = (size_t)blockIdx.x * 256 + threadIdx.x; i < TOT4;
         i += (size_t)gridDim.x * 256) {
        float4 v = (i < HALF4) ? ((const float4*)xq)[i]
                               : ((const float4*)xc)[i - HALF4];
        uint2 hq, lq;
        split4(v, hq, lq);
        Xhi[i] = hq;
        Xlo[i] = lq;
    }
}

// ---------------- weight conversion (one-shot) ----------------
__global__ void __launch_bounds__(256) k_cvtW(const float* __restrict__ W1,
                                              const float* __restrict__ W2,
                                              const float* __restrict__ W3) {
    int i = blockIdx.x * 256 + threadIdx.x;
    if (i >= 26624) return;
    float w = (i < 16384) ? W1[i] : (i < 24576 ? W2[i - 16384] : W3[i - 24576]);
    __nv_bfloat16 h = __float2bfloat16(w);
    g_Whi[i] = h;
    g_Wlo[i] = __float2bfloat16(w - __bfloat162float(h));
}

// ---------------- CSR build (per graph) + global init in block 0 ----------------
__global__ void __launch_bounds__(256) k_csr(const int* __restrict__ eq,
                                             const int* __restrict__ ec) {
    const int g = blockIdx.x;
    const int t = threadIdx.x;
    if (g == 0) {
        if (t == 0) { g_minmax[0] = 0xffffffffu; g_minmax[1] = 0u; }
        if (t < 16) g_hist[t] = 0;
    }
    const int* base = (g < B_) ? (eq + (size_t)g * 2 * E_)
                               : (ec + (size_t)(g - B_) * 2 * E_);
    const int* src = base;
    const int* dst = base + E_;

    __shared__ int   cnt[256];
    __shared__ int   scan[256];
    __shared__ int   off[256];
    __shared__ float dinv[256];

    cnt[t] = 0;
    __syncthreads();
    for (int e = t; e < E_; e += 256) atomicAdd(&cnt[dst[e]], 1);
    __syncthreads();

    float deg = (float)cnt[t] + 1.0f;
    dinv[t] = rsqrtf(deg);
    g_invdeg[g * N_ + t] = 1.0f / deg;

    int v = cnt[t];
    scan[t] = v;
    __syncthreads();
    for (int s = 1; s < 256; s <<= 1) {
        int add = (t >= s) ? scan[t - s] : 0;
        __syncthreads();
        scan[t] += add;
        __syncthreads();
    }
    int excl = scan[t] - v;
    off[t] = excl;
    g_rowptr[g * 257 + t] = excl;
    if (t == 0) g_rowptr[g * 257 + 256] = E_;
    __syncthreads();

    for (int e = t; e < E_; e += 256) {
        int d = dst[e];
        int s_ = src[e];
        int pos = atomicAdd(&off[d], 1);
        g_edge[g * E_ + pos] = make_float2(dinv[s_] * dinv[d], __int_as_float(s_));
    }
}

// ---------------- zero-smem wmma split-bf16 GEMM ----------------
// out[65536,FO] = X[65536,K] @ W[K,FO];  D = Ah*Bh + Ah*Bl + Al*Bh
// A fragments from global (reused NT times in regs); W fragments L1-resident.
template<int K, int FO>
__global__ void __launch_bounds__(256) k_gemm_tc(
    const __nv_bfloat16* __restrict__ Xhi, const __nv_bfloat16* __restrict__ Xlo,
    const __nv_bfloat16* __restrict__ Whi, const __nv_bfloat16* __restrict__ Wlo,
    float* __restrict__ out) {
    constexpr int NT = FO / 16;
    const int wid = threadIdx.x >> 5;
    const size_t r0 = (size_t)blockIdx.x * 128 + wid * 16;

    wmma::fragment<wmma::accumulator, 16, 16, 16, float> C[NT];
#pragma unroll
    for (int n = 0; n < NT; n++) wmma::fill_fragment(C[n], 0.0f);

    const __nv_bfloat16* Ah = Xhi + r0 * K;
    const __nv_bfloat16* Al = Xlo + r0 * K;

#pragma unroll
    for (int k0 = 0; k0 < K; k0 += 16) {
        wmma::fragment<wmma::matrix_a, 16, 16, 16, __nv_bfloat16, wmma::row_major> ah, al;
        wmma::load_matrix_sync(ah, Ah + k0, K);
        wmma::load_matrix_sync(al, Al + k0, K);
#pragma unroll
        for (int n = 0; n < NT; n++) {
            wmma::fragment<wmma::matrix_b, 16, 16, 16, __nv_bfloat16, wmma::row_major> bh, bl;
            wmma::load_matrix_sync(bh, Whi + (size_t)k0 * FO + n * 16, FO);
            wmma::load_matrix_sync(bl, Wlo + (size_t)k0 * FO + n * 16, FO);
            wmma::mma_sync(C[n], ah, bh, C[n]);
            wmma::mma_sync(C[n], ah, bl, C[n]);
            wmma::mma_sync(C[n], al, bh, C[n]);
        }
    }

    float* O = out + r0 * FO;
#pragma unroll
    for (int n = 0; n < NT; n++)
        wmma::store_matrix_sync(O + n * 16, C[n], FO, wmma::mem_row_major);
}

// ---------------- GCN aggregate: out = agg + h/deg + b; fp32 or bf16-hi/lo out ----------------
template<int FD, bool RELU, bool OBF16>
__global__ void __launch_bounds__(1024) k_agg(const float* __restrict__ H,
                                              const float* __restrict__ bias,
                                              float* __restrict__ outF) {
    constexpr int QPN = FD / 4;          // feature quads per node
    constexpr int NPB = 1024 / QPN;      // nodes processed concurrently
    extern __shared__ float smf[];
    float4* hsm = (float4*)smf;                       // N_*QPN float4
    float2* esm = (float2*)(smf + N_ * FD);           // E_ float2
    int*    rsm = (int*)(smf + N_ * FD + 2 * E_);     // 257

    const int g = blockIdx.x;
    const int t = threadIdx.x;

    const float4* Hg = (const float4*)(H + (size_t)g * N_ * FD);
    for (int i = t; i < N_ * QPN; i += 1024) hsm[i] = Hg[i];
    {
        const float2* Eg = g_edge + (size_t)g * E_;
        for (int i = t; i < E_; i += 1024) esm[i] = Eg[i];
    }
    for (int i = t; i < 257; i += 1024) rsm[i] = g_rowptr[g * 257 + i];
    __syncthreads();

    const int fq = t % QPN;
    const int n0 = t / QPN;
    const float4 bf = ((const float4*)bias)[fq];
    float4* OF  = (float4*)(outF + (size_t)g * N_ * FD);
    uint2*  OHI = (uint2*)g_Xhi + (size_t)g * N_ * QPN;
    uint2*  OLO = (uint2*)g_Xlo + (size_t)g * N_ * QPN;

#pragma unroll
    for (int n = n0; n < N_; n += NPB) {
        const int e0 = rsm[n], e1 = rsm[n + 1];
        float4 a0 = make_float4(0.f, 0.f, 0.f, 0.f);
        float4 a1 = make_float4(0.f, 0.f, 0.f, 0.f);
        int e = e0;
        for (; e + 1 < e1; e += 2) {
            float2 ed0 = esm[e];
            float2 ed1 = esm[e + 1];
            float4 h0 = hsm[__float_as_int(ed0.y) * QPN + fq];
            float4 h1 = hsm[__float_as_int(ed1.y) * QPN + fq];
            a0.x += h0.x * ed0.x; a0.y += h0.y * ed0.x;
            a0.z += h0.z * ed0.x; a0.w += h0.w * ed0.x;
            a1.x += h1.x * ed1.x; a1.y += h1.y * ed1.x;
            a1.z += h1.z * ed1.x; a1.w += h1.w * ed1.x;
        }
        if (e < e1) {
            float2 ed0 = esm[e];
            float4 h0 = hsm[__float_as_int(ed0.y) * QPN + fq];
            a0.x += h0.x * ed0.x; a0.y += h0.y * ed0.x;
            a0.z += h0.z * ed0.x; a0.w += h0.w * ed0.x;
        }
        const float id = g_invdeg[g * N_ + n];
        float4 hs = hsm[n * QPN + fq];
        float4 v;
        v.x = a0.x + a1.x + hs.x * id + bf.x;
        v.y = a0.y + a1.y + hs.y * id + bf.y;
        v.z = a0.z + a1.z + hs.z * id + bf.z;
        v.w = a0.w + a1.w + hs.w * id + bf.w;
        if (RELU) {
            v.x = fmaxf(v.x, 0.f); v.y = fmaxf(v.y, 0.f);
            v.z = fmaxf(v.z, 0.f); v.w = fmaxf(v.w, 0.f);
        }
        if (OBF16) {
            uint2 hq, lq;
            split4(v, hq, lq);
            OHI[n * QPN + fq] = hq;
            OLO[n * QPN + fq] = lq;
        } else {
            OF[n * QPN + fq] = v;
        }
    }
}

// ---------------- SimGNN attention pooling (f3 = 32) ----------------
__global__ void __launch_bounds__(256) k_pool(const float* __restrict__ emb,
                                              const float* __restrict__ Watt) {
    __shared__ float xs[N_ * 33];   // padded rows: conflict-free row reads
    __shared__ float colsum[32];
    __shared__ float ctx[32];
    __shared__ float score[N_];

    const int g = blockIdx.x, t = threadIdx.x;
    const float* X = emb + (size_t)g * N_ * 32;
    for (int i = t; i < N_ * 32; i += 256)
        xs[(i >> 5) * 33 + (i & 31)] = X[i];
    __syncthreads();

    if (t < 32) {
        float s = 0.f;
        for (int n = 0; n < N_; n++) s += xs[n * 33 + t];
        colsum[t] = s;
    }
    __syncthreads();
    if (t < 32) {
        float a = 0.f;
        for (int i = 0; i < 32; i++) a += colsum[i] * Watt[t * 32 + i];
        ctx[t] = tanhf(a * (1.0f / 256.0f));
    }
    __syncthreads();
    {
        float d = 0.f;
#pragma unroll
        for (int i = 0; i < 32; i++) d += xs[t * 33 + i] * ctx[i];
        score[t] = 1.0f / (1.0f + expf(-d));
    }
    __syncthreads();
    if (t < 32) {
        float s = 0.f;
        for (int n = 0; n < N_; n++) s += xs[n * 33 + t] * score[n];
        g_pool[g * 32 + t] = s;
    }
}

// ---------------- NTN: relu(e1^T W_t e2 + V_t . [e1;e2] + b_t) ----------------
__global__ void __launch_bounds__(512) k_ntn(const float* __restrict__ ntnW,
                                             const float* __restrict__ ntnV,
                                             const float* __restrict__ ntnb) {
    const int b = blockIdx.x;
    __shared__ float e1[32], e2[32];
    const int t = threadIdx.x;
    if (t < 32)      e1[t]      = g_pool[b * 32 + t];
    else if (t < 64) e2[t - 32] = g_pool[(B_ + b) * 32 + (t - 32)];
    __syncthreads();

    const int w = t >> 5, lane = t & 31;   // w = tensor neuron
    const float* Wt = ntnW + w * 1024;
    float a = 0.f;
#pragma unroll 8
    for (int j = 0; j < 32; j++) a += Wt[lane * 32 + j] * e2[j];
    float partial = e1[lane] * a
                  + e1[lane] * ntnV[w * 64 + lane]
                  + e2[lane] * ntnV[w * 64 + 32 + lane];
#pragma unroll
    for (int o = 16; o; o >>= 1)
        partial += __shfl_xor_sync(0xffffffffu, partial, o);
    if (lane == 0)
        g_scoresT[b * 16 + w] = fmaxf(partial + ntnb[w], 0.f);
}

// ---------------- pairwise dot s[b,n,m] = q_n . c_m, plus global min/max ----------------
__global__ void __launch_bounds__(256) k_pair(const float* __restrict__ emb,
                                              float* __restrict__ s) {
    __shared__ float qs[64 * 32];
    __shared__ float cs[256 * 33];
    __shared__ float wmn[8], wmx[8];

    const int b = blockIdx.y, nt = blockIdx.x;
    const int t = threadIdx.x;
    const float* Q = emb + (size_t)b * N_ * 32 + (size_t)nt * 64 * 32;
    const float* C = emb + (size_t)(B_ + b) * N_ * 32;
    for (int i = t; i < 64 * 32; i += 256) qs[i] = Q[i];
    for (int i = t; i < 256 * 32; i += 256)
        cs[(i >> 5) * 33 + (i & 31)] = C[i];
    __syncthreads();

    float cr[32];
#pragma unroll
    for (int k = 0; k < 32; k++) cr[k] = cs[t * 33 + k];

    float vmin = 3.402823466e38f, vmax = -3.402823466e38f;
    float* Sb = s + (size_t)b * N_ * N_ + (size_t)nt * 64 * N_;
    for (int n = 0; n < 64; n += 4) {
        float a0 = 0.f, a1 = 0.f, a2 = 0.f, a3 = 0.f;
#pragma unroll
        for (int k = 0; k < 32; k++) {
            float cv = cr[k];
            a0 += qs[(n + 0) * 32 + k] * cv;
            a1 += qs[(n + 1) * 32 + k] * cv;
            a2 += qs[(n + 2) * 32 + k] * cv;
            a3 += qs[(n + 3) * 32 + k] * cv;
        }
        Sb[(n + 0) * N_ + t] = a0;
        Sb[(n + 1) * N_ + t] = a1;
        Sb[(n + 2) * N_ + t] = a2;
        Sb[(n + 3) * N_ + t] = a3;
        vmin = fminf(fminf(vmin, a0), fminf(fminf(a1, a2), a3));
        vmax = fmaxf(fmaxf(vmax, a0), fmaxf(fmaxf(a1, a2), a3));
    }
#pragma unroll
    for (int o = 16; o; o >>= 1) {
        vmin = fminf(vmin, __shfl_xor_sync(0xffffffffu, vmin, o));
        vmax = fmaxf(vmax, __shfl_xor_sync(0xffffffffu, vmax, o));
    }
    if ((t & 31) == 0) { wmn[t >> 5] = vmin; wmx[t >> 5] = vmax; }
    __syncthreads();
    if (t == 0) {
        float m = wmn[0], M = wmx[0];
        for (int i = 1; i < 8; i++) { m = fminf(m, wmn[i]); M = fmaxf(M, wmx[i]); }
        atomicMin(&g_minmax[0], encf(m));
        atomicMax(&g_minmax[1], encf(M));
    }
}

// ---------------- histogram over 8.4M values, float4 loads + ballot counting ----------------
__global__ void __launch_bounds__(256) k_hist(const float* __restrict__ s) {
    __shared__ int hsm[16];
    const int t = threadIdx.x;
    if (t < 16) hsm[t] = 0;
    __syncthreads();

    const float lo = decf(g_minmax[0]);
    const float inv = 16.0f / (decf(g_minmax[1]) - lo);
    const int lane = t & 31;
    int cnt = 0;   // lane i accumulates bin i (lanes 16..31 idle)

    const float4* s4 = (const float4*)s;
    // 2097152 float4 total = 1024 blocks * 256 thr * 8 iters
    size_t idx0 = (size_t)blockIdx.x * 256 + t;
    for (int it = 0; it < 8; it++) {
        float4 v = s4[idx0 + (size_t)it * 262144];
        float vv[4] = {v.x, v.y, v.z, v.w};
#pragma unroll
        for (int j = 0; j < 4; j++) {
            int bi = (int)floorf((vv[j] - lo) * inv);
            bi = bi < 0 ? 0 : (bi > 15 ? 15 : bi);
#pragma unroll
            for (int b = 0; b < 16; b++) {
                unsigned m = __ballot_sync(0xffffffffu, bi == b);
                if (lane == b) cnt += __popc(m);
            }
        }
    }
    if (lane < 16) atomicAdd(&hsm[lane], cnt);
    __syncthreads();
    if (t < 16) atomicAdd(&g_hist[t], hsm[t]);
}

// ---------------- final MLP head ----------------
__global__ void k_final(const float* __restrict__ fc1W, const float* __restrict__ fc1b,
                        const float* __restrict__ fc2W, const float* __restrict__ fc2b,
                        float* __restrict__ out) {
    __shared__ float h[16];
    const int b = threadIdx.x;
    if (b < 16) h[b] = (float)g_hist[b] * (1.0f / 8388608.0f);
    __syncthreads();

    float sc[16];
#pragma unroll
    for (int t = 0; t < 16; t++) sc[t] = g_scoresT[b * 16 + t];

    float p = fc2b[0];
#pragma unroll
    for (int j = 0; j < 16; j++) {
        float a = fc1b[j];
#pragma unroll
        for (int t = 0; t < 16; t++) a += sc[t] * fc1W[j * 32 + t];
#pragma unroll
        for (int k = 0; k < 16; k++) a += h[k] * fc1W[j * 32 + 16 + k];
        p += fmaxf(a, 0.f) * fc2W[j];
    }
    out[b] = 1.0f / (1.0f + expf(-p));
}

// ---------------- launch ----------------
extern "C" void kernel_launch(void* const* d_in, const int* in_sizes, int n_in,
                              void* d_out, int out_size) {
    const float* xq   = (const float*)d_in[0];
    const float* xc   = (const float*)d_in[1];
    const int*   eq   = (const int*)d_in[2];
    const int*   ec   = (const int*)d_in[3];
    const float* W1   = (const float*)d_in[4];
    const float* b1   = (const float*)d_in[5];
    const float* W2   = (const float*)d_in[6];
    const float* b2   = (const float*)d_in[7];
    const float* W3   = (const float*)d_in[8];
    const float* b3   = (const float*)d_in[9];
    const float* Watt = (const float*)d_in[10];
    const float* ntnW = (const float*)d_in[11];
    const float* ntnV = (const float*)d_in[12];
    const float* ntnb = (const float*)d_in[13];
    const float* fc1W = (const float*)d_in[14];
    const float* fc1b = (const float*)d_in[15];
    const float* fc2W = (const float*)d_in[16];
    const float* fc2b = (const float*)d_in[17];
    float* out = (float*)d_out;

    float *bufA, *bufB;
    cudaGetSymbolAddress((void**)&bufA, g_bufA);
    cudaGetSymbolAddress((void**)&bufB, g_bufB);
    __nv_bfloat16 *Xhi, *Xlo, *Whi, *Wlo;
    cudaGetSymbolAddress((void**)&Xhi, g_Xhi);
    cudaGetSymbolAddress((void**)&Xlo, g_Xlo);
    cudaGetSymbolAddress((void**)&Whi, g_Whi);
    cudaGetSymbolAddress((void**)&Wlo, g_Wlo);

    constexpr int SM_A1 = (N_ * 128 + 2 * E_ + 260) * 4;    // ~145 KB
    constexpr int SM_A2 = (N_ * 64  + 2 * E_ + 260) * 4;    // ~81 KB
    constexpr int SM_A3 = (N_ * 32  + 2 * E_ + 260) * 4;    // ~49 KB

    cudaFuncSetAttribute(k_agg<128, true, true>,   cudaFuncAttributeMaxDynamicSharedMemorySize, SM_A1);
    cudaFuncSetAttribute(k_agg<64,  true, true>,   cudaFuncAttributeMaxDynamicSharedMemorySize, SM_A2);
    cudaFuncSetAttribute(k_agg<32,  false, false>, cudaFuncAttributeMaxDynamicSharedMemorySize, SM_A3);

    k_csr<<<GTOT, 256>>>(eq, ec);
    k_cvtW<<<104, 256>>>(W1, W2, W3);
    k_cvtX<<<2048, 256>>>(xq, xc);

    k_gemm_tc<128, 128><<<512, 256>>>(Xhi, Xlo, Whi, Wlo, bufA);
    k_agg<128, true, true><<<GTOT, 1024, SM_A1>>>(bufA, b1, nullptr);

    k_gemm_tc<128, 64><<<512, 256>>>(Xhi, Xlo, Whi + 16384, Wlo + 16384, bufA);
    k_agg<64, true, true><<<GTOT, 1024, SM_A2>>>(bufA, b2, nullptr);

    k_gemm_tc<64, 32><<<512, 256>>>(Xhi, Xlo, Whi + 24576, Wlo + 24576, bufA);
    k_agg<32, false, false><<<GTOT, 1024, SM_A3>>>(bufA, b3, bufB);   // bufB = final embeddings

    k_pool<<<GTOT, 256>>>(bufB, Watt);
    k_ntn<<<B_, 512>>>(ntnW, ntnV, ntnb);

    k_pair<<<dim3(4, B_), 256>>>(bufB, bufA);   // bufA reused as s [128,256,256]
    k_hist<<<1024, 256>>>(bufA);

    k_final<<<1, B_>>>(fc1W, fc1b, fc2W, fc2b, out);
}

// round 7
// speedup vs baseline: 1.2987x; 1.2987x over previous
#include <cuda_runtime.h>
#include <cuda_bf16.h>
#include <mma.h>
#include <cstdint>
#include <math.h>

using namespace nvcuda;

#define B_   128
#define N_   256
#define E_   2048
#define GTOT 256   // q graphs [0,128) + c graphs [128,256)

// ---------------- device scratch (static globals: no allocs) ----------------
__device__ float    g_bufA[GTOT * N_ * 128];   // 33.5 MB (gemm out / s matrix)
__device__ float    g_bufB[GTOT * N_ * 128];   // 33.5 MB (final embeddings)
__device__ __nv_bfloat16 g_Xhi[GTOT * N_ * 128];   // 16.8 MB bf16 hi activations
__device__ __nv_bfloat16 g_Xlo[GTOT * N_ * 128];   // 16.8 MB bf16 lo activations
__device__ __nv_bfloat16 g_Whi[26624];             // W1|W2|W3 bf16 hi
__device__ __nv_bfloat16 g_Wlo[26624];             // W1|W2|W3 bf16 lo
__device__ float2   g_edge[GTOT * E_];         // packed (coef, src-as-float-bits)
__device__ int      g_rowptr[GTOT * 257];
__device__ float    g_invdeg[GTOT * N_];
__device__ float    g_pool[GTOT * 32];
__device__ float    g_scoresT[B_ * 16];
__device__ unsigned g_minmax[2];
__device__ int      g_hist[16];

// monotone float<->uint mapping for atomicMin/Max over signed floats
__device__ __forceinline__ unsigned encf(float f) {
    unsigned u = __float_as_uint(f);
    return (u & 0x80000000u) ? ~u : (u | 0x80000000u);
}
__device__ __forceinline__ float decf(unsigned u) {
    return (u & 0x80000000u) ? __uint_as_float(u & 0x7fffffffu)
                             : __uint_as_float(~u);
}

// pack 4 floats -> (hi uint2, lo uint2) of bf16
__device__ __forceinline__ void split4(float4 v, uint2& hq, uint2& lq) {
    __nv_bfloat16 h0 = __float2bfloat16(v.x);
    __nv_bfloat16 h1 = __float2bfloat16(v.y);
    __nv_bfloat16 h2 = __float2bfloat16(v.z);
    __nv_bfloat16 h3 = __float2bfloat16(v.w);
    __nv_bfloat16 l0 = __float2bfloat16(v.x - __bfloat162float(h0));
    __nv_bfloat16 l1 = __float2bfloat16(v.y - __bfloat162float(h1));
    __nv_bfloat16 l2 = __float2bfloat16(v.z - __bfloat162float(h2));
    __nv_bfloat16 l3 = __float2bfloat16(v.w - __bfloat162float(h3));
    __nv_bfloat162 ph01(h0, h1), ph23(h2, h3), pl01(l0, l1), pl23(l2, l3);
    hq.x = *(unsigned*)&ph01; hq.y = *(unsigned*)&ph23;
    lq.x = *(unsigned*)&pl01; lq.y = *(unsigned*)&pl23;
}

// ---------------- input conversion: xq|xc fp32 -> bf16 hi/lo ----------------
__global__ void __launch_bounds__(256) k_cvtX(const float* __restrict__ xq,
                                              const float* __restrict__ xc) {
    constexpr size_t TOT4  = (size_t)GTOT * N_ * 128 / 4;   // 2,097,152
    constexpr size_t HALF4 = TOT4 / 2;
    uint2* Xhi = (uint2*)g_Xhi;
    uint2* Xlo = (uint2*)g_Xlo;
    for (size_t i = (size_t)blockIdx.x * 256 + threadIdx.x; i < TOT4;
         i += (size_t)gridDim.x * 256) {
        float4 v = (i < HALF4) ? ((const float4*)xq)[i]
                               : ((const float4*)xc)[i - HALF4];
        uint2 hq, lq;
        split4(v, hq, lq);
        Xhi[i] = hq;
        Xlo[i] = lq;
    }
}

// ---------------- weight conversion (one-shot) ----------------
__global__ void __launch_bounds__(256) k_cvtW(const float* __restrict__ W1,
                                              const float* __restrict__ W2,
                                              const float* __restrict__ W3) {
    int i = blockIdx.x * 256 + threadIdx.x;
    if (i >= 26624) return;
    float w = (i < 16384) ? W1[i] : (i < 24576 ? W2[i - 16384] : W3[i - 24576]);
    __nv_bfloat16 h = __float2bfloat16(w);
    g_Whi[i] = h;
    g_Wlo[i] = __float2bfloat16(w - __bfloat162float(h));
}

// ---------------- CSR build (per graph) + global init in block 0 ----------------
__global__ void __launch_bounds__(256) k_csr(const int* __restrict__ eq,
                                             const int* __restrict__ ec) {
    const int g = blockIdx.x;
    const int t = threadIdx.x;
    if (g == 0) {
        if (t == 0) { g_minmax[0] = 0xffffffffu; g_minmax[1] = 0u; }
        if (t < 16) g_hist[t] = 0;
    }
    const int* base = (g < B_) ? (eq + (size_t)g * 2 * E_)
                               : (ec + (size_t)(g - B_) * 2 * E_);
    const int* src = base;
    const int* dst = base + E_;

    __shared__ int   cnt[256];
    __shared__ int   scan[256];
    __shared__ int   off[256];
    __shared__ float dinv[256];

    cnt[t] = 0;
    __syncthreads();
    for (int e = t; e < E_; e += 256) atomicAdd(&cnt[dst[e]], 1);
    __syncthreads();

    float deg = (float)cnt[t] + 1.0f;
    dinv[t] = rsqrtf(deg);
    g_invdeg[g * N_ + t] = 1.0f / deg;

    int v = cnt[t];
    scan[t] = v;
    __syncthreads();
    for (int s = 1; s < 256; s <<= 1) {
        int add = (t >= s) ? scan[t - s] : 0;
        __syncthreads();
        scan[t] += add;
        __syncthreads();
    }
    int excl = scan[t] - v;
    off[t] = excl;
    g_rowptr[g * 257 + t] = excl;
    if (t == 0) g_rowptr[g * 257 + 256] = E_;
    __syncthreads();

    for (int e = t; e < E_; e += 256) {
        int d = dst[e];
        int s_ = src[e];
        int pos = atomicAdd(&off[d], 1);
        g_edge[g * E_ + pos] = make_float2(dinv[s_] * dinv[d], __int_as_float(s_));
    }
}

// ---------------- smem-staged wmma split-bf16 GEMM (pure uint4 staging) ----------------
// out[65536,FO] = X[65536,K] @ W[K,FO];  D = Ah*Bh + Ah*Bl + Al*Bh
template<int K, int FO>
__global__ void __launch_bounds__(256) k_gemm_tc(
    const __nv_bfloat16* __restrict__ Xhi, const __nv_bfloat16* __restrict__ Xlo,
    const __nv_bfloat16* __restrict__ Whi, const __nv_bfloat16* __restrict__ Wlo,
    float* __restrict__ out) {
    constexpr int LDA = K + 8;    // bf16 elems, padded vs bank conflicts
    constexpr int LDB = FO + 8;
    constexpr int KQ = K / 8;     // uint4 per A row
    constexpr int FQ = FO / 8;    // uint4 per W row
    extern __shared__ __align__(16) __nv_bfloat16 sm[];
    __nv_bfloat16* Ahi = sm;                       // 128*LDA
    __nv_bfloat16* Alo = Ahi + 128 * LDA;
    __nv_bfloat16* Bhi = Alo + 128 * LDA;          // K*LDB
    __nv_bfloat16* Blo = Bhi + K * LDB;

    const int t = threadIdx.x, wid = t >> 5;
    const size_t r0 = (size_t)blockIdx.x * 128;

    // ---- stage A (vector copy of pre-converted bf16) ----
    {
        const uint4* GH = (const uint4*)(Xhi + r0 * K);
        const uint4* GL = (const uint4*)(Xlo + r0 * K);
        for (int i = t; i < 128 * KQ; i += 256) {
            int r = i / KQ, c = i % KQ;
            ((uint4*)(Ahi + r * LDA))[c] = GH[i];
            ((uint4*)(Alo + r * LDA))[c] = GL[i];
        }
    }
    // ---- stage W ----
    {
        const uint4* GH = (const uint4*)Whi;
        const uint4* GL = (const uint4*)Wlo;
        for (int i = t; i < K * FQ; i += 256) {
            int r = i / FQ, c = i % FQ;
            ((uint4*)(Bhi + r * LDB))[c] = GH[i];
            ((uint4*)(Blo + r * LDB))[c] = GL[i];
        }
    }
    __syncthreads();

    constexpr int NT = FO / 16;
    wmma::fragment<wmma::accumulator, 16, 16, 16, float> C[NT];
#pragma unroll
    for (int n = 0; n < NT; n++) wmma::fill_fragment(C[n], 0.0f);

    const __nv_bfloat16* Ah = Ahi + (size_t)(wid * 16) * LDA;
    const __nv_bfloat16* Al = Alo + (size_t)(wid * 16) * LDA;

#pragma unroll
    for (int k0 = 0; k0 < K; k0 += 16) {
        wmma::fragment<wmma::matrix_a, 16, 16, 16, __nv_bfloat16, wmma::row_major> ah, al;
        wmma::load_matrix_sync(ah, Ah + k0, LDA);
        wmma::load_matrix_sync(al, Al + k0, LDA);
#pragma unroll
        for (int n = 0; n < NT; n++) {
            wmma::fragment<wmma::matrix_b, 16, 16, 16, __nv_bfloat16, wmma::row_major> bh, bl;
            wmma::load_matrix_sync(bh, Bhi + (size_t)k0 * LDB + n * 16, LDB);
            wmma::load_matrix_sync(bl, Blo + (size_t)k0 * LDB + n * 16, LDB);
            wmma::mma_sync(C[n], ah, bh, C[n]);
            wmma::mma_sync(C[n], ah, bl, C[n]);
            wmma::mma_sync(C[n], al, bh, C[n]);
        }
    }

    float* O = out + (r0 + wid * 16) * FO;
#pragma unroll
    for (int n = 0; n < NT; n++)
        wmma::store_matrix_sync(O + n * 16, C[n], FO, wmma::mem_row_major);
}

// ---------------- GCN aggregate: out = agg + h/deg + b; fp32 or bf16-hi/lo out ----------------
template<int FD, bool RELU, bool OBF16>
__global__ void __launch_bounds__(1024) k_agg(const float* __restrict__ H,
                                              const float* __restrict__ bias,
                                              float* __restrict__ outF) {
    constexpr int QPN = FD / 4;          // feature quads per node
    constexpr int NPB = 1024 / QPN;      // nodes processed concurrently
    extern __shared__ float smf[];
    float4* hsm = (float4*)smf;                       // N_*QPN float4
    float2* esm = (float2*)(smf + N_ * FD);           // E_ float2
    int*    rsm = (int*)(smf + N_ * FD + 2 * E_);     // 257

    const int g = blockIdx.x;
    const int t = threadIdx.x;

    const float4* Hg = (const float4*)(H + (size_t)g * N_ * FD);
    for (int i = t; i < N_ * QPN; i += 1024) hsm[i] = Hg[i];
    {
        const float2* Eg = g_edge + (size_t)g * E_;
        for (int i = t; i < E_; i += 1024) esm[i] = Eg[i];
    }
    for (int i = t; i < 257; i += 1024) rsm[i] = g_rowptr[g * 257 + i];
    __syncthreads();

    const int fq = t % QPN;
    const int n0 = t / QPN;
    const float4 bf = ((const float4*)bias)[fq];
    float4* OF  = (float4*)(outF + (size_t)g * N_ * FD);
    uint2*  OHI = (uint2*)g_Xhi + (size_t)g * N_ * QPN;
    uint2*  OLO = (uint2*)g_Xlo + (size_t)g * N_ * QPN;

#pragma unroll
    for (int n = n0; n < N_; n += NPB) {
        const int e0 = rsm[n], e1 = rsm[n + 1];
        float4 a0 = make_float4(0.f, 0.f, 0.f, 0.f);
        float4 a1 = make_float4(0.f, 0.f, 0.f, 0.f);
        int e = e0;
        for (; e + 1 < e1; e += 2) {
            float2 ed0 = esm[e];
            float2 ed1 = esm[e + 1];
            float4 h0 = hsm[__float_as_int(ed0.y) * QPN + fq];
            float4 h1 = hsm[__float_as_int(ed1.y) * QPN + fq];
            a0.x += h0.x * ed0.x; a0.y += h0.y * ed0.x;
            a0.z += h0.z * ed0.x; a0.w += h0.w * ed0.x;
            a1.x += h1.x * ed1.x; a1.y += h1.y * ed1.x;
            a1.z += h1.z * ed1.x; a1.w += h1.w * ed1.x;
        }
        if (e < e1) {
            float2 ed0 = esm[e];
            float4 h0 = hsm[__float_as_int(ed0.y) * QPN + fq];
            a0.x += h0.x * ed0.x; a0.y += h0.y * ed0.x;
            a0.z += h0.z * ed0.x; a0.w += h0.w * ed0.x;
        }
        const float id = g_invdeg[g * N_ + n];
        float4 hs = hsm[n * QPN + fq];
        float4 v;
        v.x = a0.x + a1.x + hs.x * id + bf.x;
        v.y = a0.y + a1.y + hs.y * id + bf.y;
        v.z = a0.z + a1.z + hs.z * id + bf.z;
        v.w = a0.w + a1.w + hs.w * id + bf.w;
        if (RELU) {
            v.x = fmaxf(v.x, 0.f); v.y = fmaxf(v.y, 0.f);
            v.z = fmaxf(v.z, 0.f); v.w = fmaxf(v.w, 0.f);
        }
        if (OBF16) {
            uint2 hq, lq;
            split4(v, hq, lq);
            OHI[n * QPN + fq] = hq;
            OLO[n * QPN + fq] = lq;
        } else {
            OF[n * QPN + fq] = v;
        }
    }
}

// ---------------- SimGNN attention pooling (f3 = 32) ----------------
__global__ void __launch_bounds__(256) k_pool(const float* __restrict__ emb,
                                              const float* __restrict__ Watt) {
    __shared__ float xs[N_ * 33];   // padded rows: conflict-free row reads
    __shared__ float colsum[32];
    __shared__ float ctx[32];
    __shared__ float score[N_];

    const int g = blockIdx.x, t = threadIdx.x;
    const float* X = emb + (size_t)g * N_ * 32;
    for (int i = t; i < N_ * 32; i += 256)
        xs[(i >> 5) * 33 + (i & 31)] = X[i];
    __syncthreads();

    if (t < 32) {
        float s = 0.f;
        for (int n = 0; n < N_; n++) s += xs[n * 33 + t];
        colsum[t] = s;
    }
    __syncthreads();
    if (t < 32) {
        float a = 0.f;
        for (int i = 0; i < 32; i++) a += colsum[i] * Watt[t * 32 + i];
        ctx[t] = tanhf(a * (1.0f / 256.0f));
    }
    __syncthreads();
    {
        float d = 0.f;
#pragma unroll
        for (int i = 0; i < 32; i++) d += xs[t * 33 + i] * ctx[i];
        score[t] = 1.0f / (1.0f + expf(-d));
    }
    __syncthreads();
    if (t < 32) {
        float s = 0.f;
        for (int n = 0; n < N_; n++) s += xs[n * 33 + t] * score[n];
        g_pool[g * 32 + t] = s;
    }
}

// ---------------- NTN: relu(e1^T W_t e2 + V_t . [e1;e2] + b_t) ----------------
__global__ void __launch_bounds__(512) k_ntn(const float* __restrict__ ntnW,
                                             const float* __restrict__ ntnV,
                                             const float* __restrict__ ntnb) {
    const int b = blockIdx.x;
    __shared__ float e1[32], e2[32];
    const int t = threadIdx.x;
    if (t < 32)      e1[t]      = g_pool[b * 32 + t];
    else if (t < 64) e2[t - 32] = g_pool[(B_ + b) * 32 + (t - 32)];
    __syncthreads();

    const int w = t >> 5, lane = t & 31;   // w = tensor neuron
    const float* Wt = ntnW + w * 1024;
    float a = 0.f;
#pragma unroll 8
    for (int j = 0; j < 32; j++) a += Wt[lane * 32 + j] * e2[j];
    float partial = e1[lane] * a
                  + e1[lane] * ntnV[w * 64 + lane]
                  + e2[lane] * ntnV[w * 64 + 32 + lane];
#pragma unroll
    for (int o = 16; o; o >>= 1)
        partial += __shfl_xor_sync(0xffffffffu, partial, o);
    if (lane == 0)
        g_scoresT[b * 16 + w] = fmaxf(partial + ntnb[w], 0.f);
}

// ---------------- pairwise dot s[b,n,m] = q_n . c_m, plus global min/max ----------------
__global__ void __launch_bounds__(256) k_pair(const float* __restrict__ emb,
                                              float* __restrict__ s) {
    __shared__ float qs[64 * 32];
    __shared__ float cs[256 * 33];
    __shared__ float wmn[8], wmx[8];

    const int b = blockIdx.y, nt = blockIdx.x;
    const int t = threadIdx.x;
    const float* Q = emb + (size_t)b * N_ * 32 + (size_t)nt * 64 * 32;
    const float* C = emb + (size_t)(B_ + b) * N_ * 32;
    for (int i = t; i < 64 * 32; i += 256) qs[i] = Q[i];
    for (int i = t; i < 256 * 32; i += 256)
        cs[(i >> 5) * 33 + (i & 31)] = C[i];
    __syncthreads();

    float cr[32];
#pragma unroll
    for (int k = 0; k < 32; k++) cr[k] = cs[t * 33 + k];

    float vmin = 3.402823466e38f, vmax = -3.402823466e38f;
    float* Sb = s + (size_t)b * N_ * N_ + (size_t)nt * 64 * N_;
    for (int n = 0; n < 64; n += 4) {
        float a0 = 0.f, a1 = 0.f, a2 = 0.f, a3 = 0.f;
#pragma unroll
        for (int k = 0; k < 32; k++) {
            float cv = cr[k];
            a0 += qs[(n + 0) * 32 + k] * cv;
            a1 += qs[(n + 1) * 32 + k] * cv;
            a2 += qs[(n + 2) * 32 + k] * cv;
            a3 += qs[(n + 3) * 32 + k] * cv;
        }
        Sb[(n + 0) * N_ + t] = a0;
        Sb[(n + 1) * N_ + t] = a1;
        Sb[(n + 2) * N_ + t] = a2;
        Sb[(n + 3) * N_ + t] = a3;
        vmin = fminf(fminf(vmin, a0), fminf(fminf(a1, a2), a3));
        vmax = fmaxf(fmaxf(vmax, a0), fmaxf(fmaxf(a1, a2), a3));
    }
#pragma unroll
    for (int o = 16; o; o >>= 1) {
        vmin = fminf(vmin, __shfl_xor_sync(0xffffffffu, vmin, o));
        vmax = fmaxf(vmax, __shfl_xor_sync(0xffffffffu, vmax, o));
    }
    if ((t & 31) == 0) { wmn[t >> 5] = vmin; wmx[t >> 5] = vmax; }
    __syncthreads();
    if (t == 0) {
        float m = wmn[0], M = wmx[0];
        for (int i = 1; i < 8; i++) { m = fminf(m, wmn[i]); M = fmaxf(M, wmx[i]); }
        atomicMin(&g_minmax[0], encf(m));
        atomicMax(&g_minmax[1], encf(M));
    }
}

// ---------------- histogram over 8.4M values, float4 loads + ballot counting ----------------
__global__ void __launch_bounds__(256) k_hist(const float* __restrict__ s) {
    __shared__ int hsm[16];
    const int t = threadIdx.x;
    if (t < 16) hsm[t] = 0;
    __syncthreads();

    const float lo = decf(g_minmax[0]);
    const float inv = 16.0f / (decf(g_minmax[1]) - lo);
    const int lane = t & 31;
    int cnt = 0;   // lane i accumulates bin i (lanes 16..31 idle)

    const float4* s4 = (const float4*)s;
    // 2097152 float4 total = 1024 blocks * 256 thr * 8 iters
    size_t idx0 = (size_t)blockIdx.x * 256 + t;
    for (int it = 0; it < 8; it++) {
        float4 v = s4[idx0 + (size_t)it * 262144];
        float vv[4] = {v.x, v.y, v.z, v.w};
#pragma unroll
        for (int j = 0; j < 4; j++) {
            int bi = (int)floorf((vv[j] - lo) * inv);
            bi = bi < 0 ? 0 : (bi > 15 ? 15 : bi);
#pragma unroll
            for (int b = 0; b < 16; b++) {
                unsigned m = __ballot_sync(0xffffffffu, bi == b);
                if (lane == b) cnt += __popc(m);
            }
        }
    }
    if (lane < 16) atomicAdd(&hsm[lane], cnt);
    __syncthreads();
    if (t < 16) atomicAdd(&g_hist[t], hsm[t]);
}

// ---------------- final MLP head ----------------
__global__ void k_final(const float* __restrict__ fc1W, const float* __restrict__ fc1b,
                        const float* __restrict__ fc2W, const float* __restrict__ fc2b,
                        float* __restrict__ out) {
    __shared__ float h[16];
    const int b = threadIdx.x;
    if (b < 16) h[b] = (float)g_hist[b] * (1.0f / 8388608.0f);
    __syncthreads();

    float sc[16];
#pragma unroll
    for (int t = 0; t < 16; t++) sc[t] = g_scoresT[b * 16 + t];

    float p = fc2b[0];
#pragma unroll
    for (int j = 0; j < 16; j++) {
        float a = fc1b[j];
#pragma unroll
        for (int t = 0; t < 16; t++) a += sc[t] * fc1W[j * 32 + t];
#pragma unroll
        for (int k = 0; k < 16; k++) a += h[k] * fc1W[j * 32 + 16 + k];
        p += fmaxf(a, 0.f) * fc2W[j];
    }
    out[b] = 1.0f / (1.0f + expf(-p));
}

// ---------------- launch ----------------
extern "C" void kernel_launch(void* const* d_in, const int* in_sizes, int n_in,
                              void* d_out, int out_size) {
    const float* xq   = (const float*)d_in[0];
    const float* xc   = (const float*)d_in[1];
    const int*   eq   = (const int*)d_in[2];
    const int*   ec   = (const int*)d_in[3];
    const float* W1   = (const float*)d_in[4];
    const float* b1   = (const float*)d_in[5];
    const float* W2   = (const float*)d_in[6];
    const float* b2   = (const float*)d_in[7];
    const float* W3   = (const float*)d_in[8];
    const float* b3   = (const float*)d_in[9];
    const float* Watt = (const float*)d_in[10];
    const float* ntnW = (const float*)d_in[11];
    const float* ntnV = (const float*)d_in[12];
    const float* ntnb = (const float*)d_in[13];
    const float* fc1W = (const float*)d_in[14];
    const float* fc1b = (const float*)d_in[15];
    const float* fc2W = (const float*)d_in[16];
    const float* fc2b = (const float*)d_in[17];
    float* out = (float*)d_out;

    float *bufA, *bufB;
    cudaGetSymbolAddress((void**)&bufA, g_bufA);
    cudaGetSymbolAddress((void**)&bufB, g_bufB);
    __nv_bfloat16 *Xhi, *Xlo, *Whi, *Wlo;
    cudaGetSymbolAddress((void**)&Xhi, g_Xhi);
    cudaGetSymbolAddress((void**)&Xlo, g_Xlo);
    cudaGetSymbolAddress((void**)&Whi, g_Whi);
    cudaGetSymbolAddress((void**)&Wlo, g_Wlo);

    // gemm smem: 2*128*(K+8)*2 + 2*K*(FO+8)*2 bytes
    constexpr int SM_T1 = (2 * 128 * 136 + 2 * 128 * 136) * 2;   // 139264
    constexpr int SM_T2 = (2 * 128 * 136 + 2 * 128 * 72)  * 2;   // 106496
    constexpr int SM_T3 = (2 * 128 * 72  + 2 * 64 * 40)   * 2;   // 47104
    constexpr int SM_A1 = (N_ * 128 + 2 * E_ + 260) * 4;    // ~145 KB
    constexpr int SM_A2 = (N_ * 64  + 2 * E_ + 260) * 4;    // ~81 KB
    constexpr int SM_A3 = (N_ * 32  + 2 * E_ + 260) * 4;    // ~49 KB

    cudaFuncSetAttribute(k_gemm_tc<128, 128>, cudaFuncAttributeMaxDynamicSharedMemorySize, SM_T1);
    cudaFuncSetAttribute(k_gemm_tc<128, 64>,  cudaFuncAttributeMaxDynamicSharedMemorySize, SM_T2);
    cudaFuncSetAttribute(k_gemm_tc<64,  32>,  cudaFuncAttributeMaxDynamicSharedMemorySize, SM_T3);
    cudaFuncSetAttribute(k_agg<128, true, true>,   cudaFuncAttributeMaxDynamicSharedMemorySize, SM_A1);
    cudaFuncSetAttribute(k_agg<64,  true, true>,   cudaFuncAttributeMaxDynamicSharedMemorySize, SM_A2);
    cudaFuncSetAttribute(k_agg<32,  false, false>, cudaFuncAttributeMaxDynamicSharedMemorySize, SM_A3);

    k_csr<<<GTOT, 256>>>(eq, ec);
    k_cvtW<<<104, 256>>>(W1, W2, W3);
    k_cvtX<<<2048, 256>>>(xq, xc);

    k_gemm_tc<128, 128><<<512, 256, SM_T1>>>(Xhi, Xlo, Whi, Wlo, bufA);
    k_agg<128, true, true><<<GTOT, 1024, SM_A1>>>(bufA, b1, nullptr);

    k_gemm_tc<128, 64><<<512, 256, SM_T2>>>(Xhi, Xlo, Whi + 16384, Wlo + 16384, bufA);
    k_agg<64, true, true><<<GTOT, 1024, SM_A2>>>(bufA, b2, nullptr);

    k_gemm_tc<64, 32><<<512, 256, SM_T3>>>(Xhi, Xlo, Whi + 24576, Wlo + 24576, bufA);
    k_agg<32, false, false><<<GTOT, 1024, SM_A3>>>(bufA, b3, bufB);   // bufB = final embeddings

    k_pool<<<GTOT, 256>>>(bufB, Watt);
    k_ntn<<<B_, 512>>>(ntnW, ntnV, ntnb);

    k_pair<<<dim3(4, B_), 256>>>(bufB, bufA);   // bufA reused as s [128,256,256]
    k_hist<<<1024, 256>>>(bufA);

    k_final<<<1, B_>>>(fc1W, fc1b, fc2W, fc2b, out);
}

// round 8
// speedup vs baseline: 1.4552x; 1.1205x over previous
#include <cuda_runtime.h>
#include <cuda_bf16.h>
#include <mma.h>
#include <cstdint>
#include <math.h>

using namespace nvcuda;

#define B_   128
#define N_   256
#define E_   2048
#define GTOT 256   // q graphs [0,128) + c graphs [128,256)

// ---------------- device scratch (static globals: no allocs) ----------------
__device__ float    g_bufA[GTOT * N_ * 128];   // 33.5 MB (s matrix)
__device__ float    g_bufB[GTOT * N_ * 32];    //  8.4 MB (final embeddings)
__device__ __nv_bfloat16 g_Xhi[GTOT * N_ * 128];   // layer1 out hi (128-d)
__device__ __nv_bfloat16 g_Xlo[GTOT * N_ * 128];
__device__ __nv_bfloat16 g_Yhi[GTOT * N_ * 64];    // layer2 out hi (64-d)
__device__ __nv_bfloat16 g_Ylo[GTOT * N_ * 64];
__device__ __nv_bfloat16 g_Whi[26624];             // W1|W2|W3 bf16 hi
__device__ __nv_bfloat16 g_Wlo[26624];             // W1|W2|W3 bf16 lo
__device__ float2   g_edge[GTOT * E_];         // packed (coef, src-as-float-bits)
__device__ int      g_rowptr[GTOT * 257];
__device__ float    g_invdeg[GTOT * N_];
__device__ float    g_pool[GTOT * 32];
__device__ float    g_scoresT[B_ * 16];
__device__ unsigned g_minmax[2];
__device__ int      g_hist[16];

// monotone float<->uint mapping for atomicMin/Max over signed floats
__device__ __forceinline__ unsigned encf(float f) {
    unsigned u = __float_as_uint(f);
    return (u & 0x80000000u) ? ~u : (u | 0x80000000u);
}
__device__ __forceinline__ float decf(unsigned u) {
    return (u & 0x80000000u) ? __uint_as_float(u & 0x7fffffffu)
                             : __uint_as_float(~u);
}

// pack 4 floats -> (hi uint2, lo uint2) of bf16
__device__ __forceinline__ void split4(float4 v, uint2& hq, uint2& lq) {
    __nv_bfloat16 h0 = __float2bfloat16(v.x);
    __nv_bfloat16 h1 = __float2bfloat16(v.y);
    __nv_bfloat16 h2 = __float2bfloat16(v.z);
    __nv_bfloat16 h3 = __float2bfloat16(v.w);
    __nv_bfloat16 l0 = __float2bfloat16(v.x - __bfloat162float(h0));
    __nv_bfloat16 l1 = __float2bfloat16(v.y - __bfloat162float(h1));
    __nv_bfloat16 l2 = __float2bfloat16(v.z - __bfloat162float(h2));
    __nv_bfloat16 l3 = __float2bfloat16(v.w - __bfloat162float(h3));
    __nv_bfloat162 ph01(h0, h1), ph23(h2, h3), pl01(l0, l1), pl23(l2, l3);
    hq.x = *(unsigned*)&ph01; hq.y = *(unsigned*)&ph23;
    lq.x = *(unsigned*)&pl01; lq.y = *(unsigned*)&pl23;
}

// ---------------- weight conversion (one-shot) ----------------
__global__ void __launch_bounds__(256) k_cvtW(const float* __restrict__ W1,
                                              const float* __restrict__ W2,
                                              const float* __restrict__ W3) {
    int i = blockIdx.x * 256 + threadIdx.x;
    if (i >= 26624) return;
    float w = (i < 16384) ? W1[i] : (i < 24576 ? W2[i - 16384] : W3[i - 24576]);
    __nv_bfloat16 h = __float2bfloat16(w);
    g_Whi[i] = h;
    g_Wlo[i] = __float2bfloat16(w - __bfloat162float(h));
}

// ---------------- CSR build (per graph) + global init in block 0 ----------------
__global__ void __launch_bounds__(256) k_csr(const int* __restrict__ eq,
                                             const int* __restrict__ ec) {
    const int g = blockIdx.x;
    const int t = threadIdx.x;
    if (g == 0) {
        if (t == 0) { g_minmax[0] = 0xffffffffu; g_minmax[1] = 0u; }
        if (t < 16) g_hist[t] = 0;
    }
    const int* base = (g < B_) ? (eq + (size_t)g * 2 * E_)
                               : (ec + (size_t)(g - B_) * 2 * E_);
    const int* src = base;
    const int* dst = base + E_;

    __shared__ int   cnt[256];
    __shared__ int   scan[256];
    __shared__ int   off[256];
    __shared__ float dinv[256];

    cnt[t] = 0;
    __syncthreads();
    for (int e = t; e < E_; e += 256) atomicAdd(&cnt[dst[e]], 1);
    __syncthreads();

    float deg = (float)cnt[t] + 1.0f;
    dinv[t] = rsqrtf(deg);
    g_invdeg[g * N_ + t] = 1.0f / deg;

    int v = cnt[t];
    scan[t] = v;
    __syncthreads();
    for (int s = 1; s < 256; s <<= 1) {
        int add = (t >= s) ? scan[t - s] : 0;
        __syncthreads();
        scan[t] += add;
        __syncthreads();
    }
    int excl = scan[t] - v;
    off[t] = excl;
    g_rowptr[g * 257 + t] = excl;
    if (t == 0) g_rowptr[g * 257 + 256] = E_;
    __syncthreads();

    for (int e = t; e < E_; e += 256) {
        int d = dst[e];
        int s_ = src[e];
        int pos = atomicAdd(&off[d], 1);
        g_edge[g * E_ + pos] = make_float2(dinv[s_] * dinv[d], __int_as_float(s_));
    }
}

// ---------------- fused GCN layer: GEMM (wmma split-bf16) + aggregate, per graph ----------------
// One 512-thread CTA per graph: stage X/W -> 16-warp wmma -> H in smem -> CSR agg -> out.
template<int K, int FO, int LAYER>
__global__ void __launch_bounds__(512) k_fused(
    const float* __restrict__ in0, const float* __restrict__ in1,        // L1: xq,xc
    const __nv_bfloat16* __restrict__ inHi, const __nv_bfloat16* __restrict__ inLo, // L2/3
    const __nv_bfloat16* __restrict__ Whi_, const __nv_bfloat16* __restrict__ Wlo_,
    const float* __restrict__ bias,
    __nv_bfloat16* __restrict__ outHi, __nv_bfloat16* __restrict__ outLo, // L1/2
    float* __restrict__ outF)                                             // L3
{
    constexpr int LDA = K + 8;
    constexpr int LDB = FO + 8;
    extern __shared__ __align__(16) char smc[];
    __nv_bfloat16* Ahi = (__nv_bfloat16*)smc;          // 256*LDA
    __nv_bfloat16* Alo = Ahi + 256 * LDA;
    __nv_bfloat16* Bhi = Alo + 256 * LDA;              // K*LDB
    __nv_bfloat16* Blo = Bhi + K * LDB;
    float2* esm = (float2*)(Blo + K * LDB);            // E_
    int*    rsm = (int*)(esm + E_);                    // 258 (257 used)
    float*  dsm = (float*)(rsm + 258);                 // 256

    const int g = blockIdx.x;
    const int t = threadIdx.x;
    const int wid = t >> 5;

    // ---- stage A ----
    if (LAYER == 1) {
        const float* X = (g < B_) ? in0 + (size_t)g * N_ * K
                                  : in1 + (size_t)(g - B_) * N_ * K;
        const float4* X4 = (const float4*)X;
        constexpr int KQ = K / 4;
        for (int i = t; i < N_ * KQ; i += 512) {
            int r = i / KQ, c = i % KQ;
            uint2 hq, lq;
            split4(X4[i], hq, lq);
            ((uint2*)(Ahi + r * LDA))[c] = hq;
            ((uint2*)(Alo + r * LDA))[c] = lq;
        }
    } else {
        constexpr int KQ = K / 8;
        const uint4* GH = (const uint4*)(inHi + (size_t)g * N_ * K);
        const uint4* GL = (const uint4*)(inLo + (size_t)g * N_ * K);
        for (int i = t; i < N_ * KQ; i += 512) {
            int r = i / KQ, c = i % KQ;
            ((uint4*)(Ahi + r * LDA))[c] = GH[i];
            ((uint4*)(Alo + r * LDA))[c] = GL[i];
        }
    }
    // ---- stage W ----
    {
        constexpr int FQ = FO / 8;
        const uint4* GH = (const uint4*)Whi_;
        const uint4* GL = (const uint4*)Wlo_;
        for (int i = t; i < K * FQ; i += 512) {
            int r = i / FQ, c = i % FQ;
            ((uint4*)(Bhi + r * LDB))[c] = GH[i];
            ((uint4*)(Blo + r * LDB))[c] = GL[i];
        }
    }
    // ---- stage edges / rowptr / invdeg ----
    for (int i = t; i < E_; i += 512) esm[i] = g_edge[(size_t)g * E_ + i];
    for (int i = t; i < 257; i += 512) rsm[i] = g_rowptr[g * 257 + i];
    for (int i = t; i < 256; i += 512) dsm[i] = g_invdeg[g * N_ + i];
    __syncthreads();

    // ---- wmma GEMM: 16 warps x 16 rows ----
    constexpr int NT = FO / 16;
    wmma::fragment<wmma::accumulator, 16, 16, 16, float> C[NT];
#pragma unroll
    for (int n = 0; n < NT; n++) wmma::fill_fragment(C[n], 0.0f);

    const __nv_bfloat16* Ah = Ahi + (size_t)(wid * 16) * LDA;
    const __nv_bfloat16* Al = Alo + (size_t)(wid * 16) * LDA;

#pragma unroll
    for (int k0 = 0; k0 < K; k0 += 16) {
        wmma::fragment<wmma::matrix_a, 16, 16, 16, __nv_bfloat16, wmma::row_major> ah, al;
        wmma::load_matrix_sync(ah, Ah + k0, LDA);
        wmma::load_matrix_sync(al, Al + k0, LDA);
#pragma unroll
        for (int n = 0; n < NT; n++) {
            wmma::fragment<wmma::matrix_b, 16, 16, 16, __nv_bfloat16, wmma::row_major> bh, bl;
            wmma::load_matrix_sync(bh, Bhi + (size_t)k0 * LDB + n * 16, LDB);
            wmma::load_matrix_sync(bl, Blo + (size_t)k0 * LDB + n * 16, LDB);
            wmma::mma_sync(C[n], ah, bh, C[n]);
            wmma::mma_sync(C[n], ah, bl, C[n]);
            wmma::mma_sync(C[n], al, bh, C[n]);
        }
    }
    __syncthreads();   // all A/W smem reads done

    // ---- store H fp32 into smem (reusing A region) ----
    float* Hs = (float*)smc;   // 256*FO fp32 <= A region
#pragma unroll
    for (int n = 0; n < NT; n++)
        wmma::store_matrix_sync(Hs + (size_t)(wid * 16) * FO + n * 16, C[n],
                                FO, wmma::mem_row_major);
    __syncthreads();

    // ---- aggregate from smem H ----
    constexpr int QPN = FO / 4;
    constexpr int NPB = 512 / QPN;
    const int fq = t % QPN;
    const int n0 = t / QPN;
    const float4 bf = ((const float4*)bias)[fq];
    const float4* h4 = (const float4*)Hs;

    uint2* OHI = (uint2*)outHi + (size_t)g * N_ * QPN;
    uint2* OLO = (uint2*)outLo + (size_t)g * N_ * QPN;
    float4* OF = (LAYER == 3) ? (float4*)(outF + (size_t)g * N_ * FO) : nullptr;

    for (int n = n0; n < N_; n += NPB) {
        const int e0 = rsm[n], e1 = rsm[n + 1];
        float4 a0 = make_float4(0.f, 0.f, 0.f, 0.f);
        float4 a1 = make_float4(0.f, 0.f, 0.f, 0.f);
        int e = e0;
        for (; e + 1 < e1; e += 2) {
            float2 ed0 = esm[e];
            float2 ed1 = esm[e + 1];
            float4 h0 = h4[__float_as_int(ed0.y) * QPN + fq];
            float4 h1 = h4[__float_as_int(ed1.y) * QPN + fq];
            a0.x += h0.x * ed0.x; a0.y += h0.y * ed0.x;
            a0.z += h0.z * ed0.x; a0.w += h0.w * ed0.x;
            a1.x += h1.x * ed1.x; a1.y += h1.y * ed1.x;
            a1.z += h1.z * ed1.x; a1.w += h1.w * ed1.x;
        }
        if (e < e1) {
            float2 ed0 = esm[e];
            float4 h0 = h4[__float_as_int(ed0.y) * QPN + fq];
            a0.x += h0.x * ed0.x; a0.y += h0.y * ed0.x;
            a0.z += h0.z * ed0.x; a0.w += h0.w * ed0.x;
        }
        const float id = dsm[n];
        float4 hs = h4[n * QPN + fq];
        float4 v;
        v.x = a0.x + a1.x + hs.x * id + bf.x;
        v.y = a0.y + a1.y + hs.y * id + bf.y;
        v.z = a0.z + a1.z + hs.z * id + bf.z;
        v.w = a0.w + a1.w + hs.w * id + bf.w;
        if (LAYER < 3) {
            v.x = fmaxf(v.x, 0.f); v.y = fmaxf(v.y, 0.f);
            v.z = fmaxf(v.z, 0.f); v.w = fmaxf(v.w, 0.f);
            uint2 hq, lq;
            split4(v, hq, lq);
            OHI[n * QPN + fq] = hq;
            OLO[n * QPN + fq] = lq;
        } else {
            OF[n * QPN + fq] = v;
        }
    }
}

// ---------------- SimGNN attention pooling (f3 = 32) ----------------
__global__ void __launch_bounds__(256) k_pool(const float* __restrict__ emb,
                                              const float* __restrict__ Watt) {
    __shared__ float xs[N_ * 33];   // padded rows: conflict-free row reads
    __shared__ float colsum[32];
    __shared__ float ctx[32];
    __shared__ float score[N_];

    const int g = blockIdx.x, t = threadIdx.x;
    const float* X = emb + (size_t)g * N_ * 32;
    for (int i = t; i < N_ * 32; i += 256)
        xs[(i >> 5) * 33 + (i & 31)] = X[i];
    __syncthreads();

    if (t < 32) {
        float s = 0.f;
        for (int n = 0; n < N_; n++) s += xs[n * 33 + t];
        colsum[t] = s;
    }
    __syncthreads();
    if (t < 32) {
        float a = 0.f;
        for (int i = 0; i < 32; i++) a += colsum[i] * Watt[t * 32 + i];
        ctx[t] = tanhf(a * (1.0f / 256.0f));
    }
    __syncthreads();
    {
        float d = 0.f;
#pragma unroll
        for (int i = 0; i < 32; i++) d += xs[t * 33 + i] * ctx[i];
        score[t] = 1.0f / (1.0f + expf(-d));
    }
    __syncthreads();
    if (t < 32) {
        float s = 0.f;
        for (int n = 0; n < N_; n++) s += xs[n * 33 + t] * score[n];
        g_pool[g * 32 + t] = s;
    }
}

// ---------------- NTN: relu(e1^T W_t e2 + V_t . [e1;e2] + b_t) ----------------
__global__ void __launch_bounds__(512) k_ntn(const float* __restrict__ ntnW,
                                             const float* __restrict__ ntnV,
                                             const float* __restrict__ ntnb) {
    const int b = blockIdx.x;
    __shared__ float e1[32], e2[32];
    const int t = threadIdx.x;
    if (t < 32)      e1[t]      = g_pool[b * 32 + t];
    else if (t < 64) e2[t - 32] = g_pool[(B_ + b) * 32 + (t - 32)];
    __syncthreads();

    const int w = t >> 5, lane = t & 31;   // w = tensor neuron
    const float* Wt = ntnW + w * 1024;
    float a = 0.f;
#pragma unroll 8
    for (int j = 0; j < 32; j++) a += Wt[lane * 32 + j] * e2[j];
    float partial = e1[lane] * a
                  + e1[lane] * ntnV[w * 64 + lane]
                  + e2[lane] * ntnV[w * 64 + 32 + lane];
#pragma unroll
    for (int o = 16; o; o >>= 1)
        partial += __shfl_xor_sync(0xffffffffu, partial, o);
    if (lane == 0)
        g_scoresT[b * 16 + w] = fmaxf(partial + ntnb[w], 0.f);
}

// ---------------- pairwise dot s[b,n,m] = q_n . c_m, plus global min/max ----------------
__global__ void __launch_bounds__(256) k_pair(const float* __restrict__ emb,
                                              float* __restrict__ s) {
    __shared__ float qs[64 * 32];
    __shared__ float cs[256 * 33];
    __shared__ float wmn[8], wmx[8];

    const int b = blockIdx.y, nt = blockIdx.x;
    const int t = threadIdx.x;
    const float* Q = emb + (size_t)b * N_ * 32 + (size_t)nt * 64 * 32;
    const float* C = emb + (size_t)(B_ + b) * N_ * 32;
    for (int i = t; i < 64 * 32; i += 256) qs[i] = Q[i];
    for (int i = t; i < 256 * 32; i += 256)
        cs[(i >> 5) * 33 + (i & 31)] = C[i];
    __syncthreads();

    float cr[32];
#pragma unroll
    for (int k = 0; k < 32; k++) cr[k] = cs[t * 33 + k];

    float vmin = 3.402823466e38f, vmax = -3.402823466e38f;
    float* Sb = s + (size_t)b * N_ * N_ + (size_t)nt * 64 * N_;
    for (int n = 0; n < 64; n += 4) {
        float a0 = 0.f, a1 = 0.f, a2 = 0.f, a3 = 0.f;
#pragma unroll
        for (int k = 0; k < 32; k++) {
            float cv = cr[k];
            a0 += qs[(n + 0) * 32 + k] * cv;
            a1 += qs[(n + 1) * 32 + k] * cv;
            a2 += qs[(n + 2) * 32 + k] * cv;
            a3 += qs[(n + 3) * 32 + k] * cv;
        }
        Sb[(n + 0) * N_ + t] = a0;
        Sb[(n + 1) * N_ + t] = a1;
        Sb[(n + 2) * N_ + t] = a2;
        Sb[(n + 3) * N_ + t] = a3;
        vmin = fminf(fminf(vmin, a0), fminf(fminf(a1, a2), a3));
        vmax = fmaxf(fmaxf(vmax, a0), fmaxf(fmaxf(a1, a2), a3));
    }
#pragma unroll
    for (int o = 16; o; o >>= 1) {
        vmin = fminf(vmin, __shfl_xor_sync(0xffffffffu, vmin, o));
        vmax = fmaxf(vmax, __shfl_xor_sync(0xffffffffu, vmax, o));
    }
    if ((t & 31) == 0) { wmn[t >> 5] = vmin; wmx[t >> 5] = vmax; }
    __syncthreads();
    if (t == 0) {
        float m = wmn[0], M = wmx[0];
        for (int i = 1; i < 8; i++) { m = fminf(m, wmn[i]); M = fmaxf(M, wmx[i]); }
        atomicMin(&g_minmax[0], encf(m));
        atomicMax(&g_minmax[1], encf(M));
    }
}

// ---------------- histogram over 8.4M values, float4 loads + ballot counting ----------------
__global__ void __launch_bounds__(256) k_hist(const float* __restrict__ s) {
    __shared__ int hsm[16];
    const int t = threadIdx.x;
    if (t < 16) hsm[t] = 0;
    __syncthreads();

    const float lo = decf(g_minmax[0]);
    const float inv = 16.0f / (decf(g_minmax[1]) - lo);
    const int lane = t & 31;
    int cnt = 0;   // lane i accumulates bin i (lanes 16..31 idle)

    const float4* s4 = (const float4*)s;
    // 2097152 float4 total = 1024 blocks * 256 thr * 8 iters
    size_t idx0 = (size_t)blockIdx.x * 256 + t;
    for (int it = 0; it < 8; it++) {
        float4 v = s4[idx0 + (size_t)it * 262144];
        float vv[4] = {v.x, v.y, v.z, v.w};
#pragma unroll
        for (int j = 0; j < 4; j++) {
            int bi = (int)floorf((vv[j] - lo) * inv);
            bi = bi < 0 ? 0 : (bi > 15 ? 15 : bi);
#pragma unroll
            for (int b = 0; b < 16; b++) {
                unsigned m = __ballot_sync(0xffffffffu, bi == b);
                if (lane == b) cnt += __popc(m);
            }
        }
    }
    if (lane < 16) atomicAdd(&hsm[lane], cnt);
    __syncthreads();
    if (t < 16) atomicAdd(&g_hist[t], hsm[t]);
}

// ---------------- final MLP head ----------------
__global__ void k_final(const float* __restrict__ fc1W, const float* __restrict__ fc1b,
                        const float* __restrict__ fc2W, const float* __restrict__ fc2b,
                        float* __restrict__ out) {
    __shared__ float h[16];
    const int b = threadIdx.x;
    if (b < 16) h[b] = (float)g_hist[b] * (1.0f / 8388608.0f);
    __syncthreads();

    float sc[16];
#pragma unroll
    for (int t = 0; t < 16; t++) sc[t] = g_scoresT[b * 16 + t];

    float p = fc2b[0];
#pragma unroll
    for (int j = 0; j < 16; j++) {
        float a = fc1b[j];
#pragma unroll
        for (int t = 0; t < 16; t++) a += sc[t] * fc1W[j * 32 + t];
#pragma unroll
        for (int k = 0; k < 16; k++) a += h[k] * fc1W[j * 32 + 16 + k];
        p += fmaxf(a, 0.f) * fc2W[j];
    }
    out[b] = 1.0f / (1.0f + expf(-p));
}

// ---------------- launch ----------------
extern "C" void kernel_launch(void* const* d_in, const int* in_sizes, int n_in,
                              void* d_out, int out_size) {
    const float* xq   = (const float*)d_in[0];
    const float* xc   = (const float*)d_in[1];
    const int*   eq   = (const int*)d_in[2];
    const int*   ec   = (const int*)d_in[3];
    const float* W1   = (const float*)d_in[4];
    const float* b1   = (const float*)d_in[5];
    const float* W2   = (const float*)d_in[6];
    const float* b2   = (const float*)d_in[7];
    const float* W3   = (const float*)d_in[8];
    const float* b3   = (const float*)d_in[9];
    const float* Watt = (const float*)d_in[10];
    const float* ntnW = (const float*)d_in[11];
    const float* ntnV = (const float*)d_in[12];
    const float* ntnb = (const float*)d_in[13];
    const float* fc1W = (const float*)d_in[14];
    const float* fc1b = (const float*)d_in[15];
    const float* fc2W = (const float*)d_in[16];
    const float* fc2b = (const float*)d_in[17];
    float* out = (float*)d_out;

    float *bufA, *bufB;
    cudaGetSymbolAddress((void**)&bufA, g_bufA);
    cudaGetSymbolAddress((void**)&bufB, g_bufB);
    __nv_bfloat16 *Xhi, *Xlo, *Yhi, *Ylo, *Whi, *Wlo;
    cudaGetSymbolAddress((void**)&Xhi, g_Xhi);
    cudaGetSymbolAddress((void**)&Xlo, g_Xlo);
    cudaGetSymbolAddress((void**)&Yhi, g_Yhi);
    cudaGetSymbolAddress((void**)&Ylo, g_Ylo);
    cudaGetSymbolAddress((void**)&Whi, g_Whi);
    cudaGetSymbolAddress((void**)&Wlo, g_Wlo);

    // smem: A(2*256*LDA*2) + W(2*K*LDB*2) + edges(E*8) + rowptr(258*4) + invdeg(256*4)
    constexpr int EDGE = E_ * 8 + 258 * 4 + 256 * 4;                 // 18,440
    constexpr int SMF1 = (2 * 256 * 136 + 2 * 128 * 136) * 2 + EDGE; // 227,336
    constexpr int SMF2 = (2 * 256 * 136 + 2 * 128 * 72)  * 2 + EDGE; // 194,568
    constexpr int SMF3 = (2 * 256 * 72  + 2 * 64 * 40)   * 2 + EDGE; // 102,408

    cudaFuncSetAttribute(k_fused<128, 128, 1>, cudaFuncAttributeMaxDynamicSharedMemorySize, SMF1);
    cudaFuncSetAttribute(k_fused<128, 64,  2>, cudaFuncAttributeMaxDynamicSharedMemorySize, SMF2);
    cudaFuncSetAttribute(k_fused<64,  32,  3>, cudaFuncAttributeMaxDynamicSharedMemorySize, SMF3);

    k_csr<<<GTOT, 256>>>(eq, ec);
    k_cvtW<<<104, 256>>>(W1, W2, W3);

    k_fused<128, 128, 1><<<GTOT, 512, SMF1>>>(xq, xc, nullptr, nullptr,
                                              Whi, Wlo, b1, Xhi, Xlo, nullptr);
    k_fused<128, 64, 2><<<GTOT, 512, SMF2>>>(nullptr, nullptr, Xhi, Xlo,
                                             Whi + 16384, Wlo + 16384, b2, Yhi, Ylo, nullptr);
    k_fused<64, 32, 3><<<GTOT, 512, SMF3>>>(nullptr, nullptr, Yhi, Ylo,
                                            Whi + 24576, Wlo + 24576, b3,
                                            nullptr, nullptr, bufB);

    k_pool<<<GTOT, 256>>>(bufB, Watt);
    k_ntn<<<B_, 512>>>(ntnW, ntnV, ntnb);

    k_pair<<<dim3(4, B_), 256>>>(bufB, bufA);   // bufA reused as s [128,256,256]
    k_hist<<<1024, 256>>>(bufA);

    k_final<<<1, B_>>>(fc1W, fc1b, fc2W, fc2b, out);
}